// round 16
// baseline (speedup 1.0000x reference)
#include <cuda_runtime.h>
#include <cstdint>

#define T_TOK 2048
#define DDIM  1024
#define FDIM  4096
#define NEXP  8
#define CAP   2048

// ---------------- scratch (device globals; no allocations) ----------------
__device__ int   g_cnt[NEXP];
__device__ int   g_tok[NEXP][CAP];
__device__ float g_wt [NEXP][CAP];
__device__ float g_X  [(size_t)T_TOK * DDIM];          // tf32-rounded X
__device__ float g_W1r[(size_t)NEXP * DDIM * FDIM];    // tf32-rounded weights (same layout)
__device__ float g_W3r[(size_t)NEXP * DDIM * FDIM];
__device__ float g_W2r[(size_t)NEXP * FDIM * DDIM];
__device__ float g_H  [(size_t)NEXP * CAP * FDIM];     // tf32-rounded H

// ---------------- helpers ----------------
__device__ __forceinline__ uint32_t sptr(const void* p){
    return (uint32_t)__cvta_generic_to_shared(p);
}
__device__ __forceinline__ uint32_t f2tf(float f){
    uint32_t u; asm("cvt.rna.tf32.f32 %0, %1;" : "=r"(u) : "f"(f)); return u;
}
#define CPA16(dst, src) asm volatile("cp.async.cg.shared.global [%0], [%1], 16;" :: "r"(dst), "l"(src))
#define CPCOMMIT()      asm volatile("cp.async.commit_group;")
#define CPWAIT1()       asm volatile("cp.async.wait_group 1;")

__device__ __forceinline__ void mma8(float* c, const uint32_t* a, uint32_t b0, uint32_t b1){
    asm volatile("mma.sync.aligned.m16n8k8.row.col.f32.tf32.tf32.f32 "
        "{%0,%1,%2,%3}, {%4,%5,%6,%7}, {%8,%9}, {%0,%1,%2,%3};"
        : "+f"(c[0]),"+f"(c[1]),"+f"(c[2]),"+f"(c[3])
        : "r"(a[0]),"r"(a[1]),"r"(a[2]),"r"(a[3]), "r"(b0),"r"(b1));
}

// ---------------- kernel 0: zero output + counters ----------------
__global__ void k_zero(float4* out, int n4){
    int i = blockIdx.x * 256 + threadIdx.x;
    if (i < NEXP) g_cnt[i] = 0;
    if (i < n4) out[i] = make_float4(0.f, 0.f, 0.f, 0.f);
}

// ---------------- kernel 0b: stream-round fp32 -> tf32 (grid-stride) ------
__global__ void k_round(const float4* __restrict__ src, float4* __restrict__ dst, int n4){
    int stride = gridDim.x * 256;
    for (int i = blockIdx.x * 256 + threadIdx.x; i < n4; i += stride){
        float4 v = src[i];
        v.x = __uint_as_float(f2tf(v.x));
        v.y = __uint_as_float(f2tf(v.y));
        v.z = __uint_as_float(f2tf(v.z));
        v.w = __uint_as_float(f2tf(v.w));
        dst[i] = v;
    }
}

// ---------------- kernel 1: routing (1 warp per token) ----------------
__global__ void k_route(const float* __restrict__ x, const float* __restrict__ gw){
    const int t    = blockIdx.x * 8 + (threadIdx.x >> 5);
    const int lane = threadIdx.x & 31;
    const float* xr = x + (size_t)t * DDIM;

    float acc[NEXP];
    #pragma unroll
    for (int e = 0; e < NEXP; e++) acc[e] = 0.f;

    for (int i = 0; i < DDIM / 32; i++){
        float xv = xr[i * 32 + lane];
        const float* g = gw + (size_t)(i * 32 + lane) * NEXP;
        #pragma unroll
        for (int e = 0; e < NEXP; e++) acc[e] += xv * g[e];
    }
    #pragma unroll
    for (int e = 0; e < NEXP; e++){
        float v = acc[e];
        #pragma unroll
        for (int off = 16; off > 0; off >>= 1) v += __shfl_xor_sync(0xffffffffu, v, off);
        acc[e] = v;
    }
    if (lane == 0){
        int i0 = 0; float l0 = acc[0];
        #pragma unroll
        for (int e = 1; e < NEXP; e++) if (acc[e] > l0){ l0 = acc[e]; i0 = e; }
        int i1 = -1; float l1 = -3.4e38f;
        #pragma unroll
        for (int e = 0; e < NEXP; e++) if (e != i0 && acc[e] > l1){ l1 = acc[e]; i1 = e; }
        // softmax + top2 renorm == logistic on top-2 logit gap
        float r  = __expf(l1 - l0);
        float w0 = 1.f / (1.f + r);
        float w1 = r * w0;
        int p0 = atomicAdd(&g_cnt[i0], 1);
        g_tok[i0][p0] = t;  g_wt[i0][p0] = w0;
        int p1 = atomicAdd(&g_cnt[i1], 1);
        g_tok[i1][p1] = t;  g_wt[i1][p1] = w1;
    }
}

// ---------------- kernel 2: gathered dual GEMM (X@W1, X@W3) + SwiGLU -> H ----
// BM=128, BN=64 (each of W1/W3), BK=32, 256 thr, warp grid 4(M)x2(N),
// warp tile 32x32 per matrix.  All operands pre-rounded to tf32 -> no CVT
// in the inner loop.  smem strides 36 / 72 (≡8 mod 32) -> conflict-free.
__global__ void __launch_bounds__(256, 2) k_gemm1(
    const float* __restrict__ x, const float* __restrict__ w1g,
    const float* __restrict__ w3g)
{
    const int e   = blockIdx.z;
    const int cnt = g_cnt[e];
    const int m0  = blockIdx.x * 128;
    if (m0 >= cnt) return;
    const int n0  = blockIdx.y * 64;

    extern __shared__ float sm[];
    const int tid = threadIdx.x, lane = tid & 31, wid = tid >> 5;
    const int wm = wid & 3, wn = wid >> 2;

    const int am  = tid & 127;
    const int arh = tid >> 7;            // 0/1
    const int slot = m0 + am;
    const int tok  = (slot < cnt) ? g_tok[e][slot] : 0;
    const float* asrc = x + (size_t)tok * DDIM;

    const float* w1e = w1g + (size_t)e * DDIM * FDIM;
    const float* w3e = w3g + (size_t)e * DDIM * FDIM;

    float acc1[2][4][4], acc3[2][4][4];
    #pragma unroll
    for (int i = 0; i < 2; i++)
        #pragma unroll
        for (int j = 0; j < 4; j++)
            #pragma unroll
            for (int k = 0; k < 4; k++){ acc1[i][j][k] = 0.f; acc3[i][j][k] = 0.f; }

    auto load_chunk = [&](int kc, int stg){
        float* As = sm + stg * 9216;
        float* B1 = As + 4608;
        float* B3 = As + 6912;
        const int k0 = kc * 32;
        #pragma unroll
        for (int i = 0; i < 4; i++){
            int kq = arh + 2 * i;
            CPA16(sptr(As + am * 36 + kq * 4), asrc + k0 + kq * 4);
        }
        const int bk = tid >> 4;     // 0..15
        const int n4 = tid & 15;
        const float* s1 = w1e + (size_t)(k0 + bk) * FDIM + n0 + n4 * 4;
        CPA16(sptr(B1 + bk * 72 + n4 * 4),        s1);
        CPA16(sptr(B1 + (bk + 16) * 72 + n4 * 4), s1 + (size_t)16 * FDIM);
        const float* s3 = w3e + (size_t)(k0 + bk) * FDIM + n0 + n4 * 4;
        CPA16(sptr(B3 + bk * 72 + n4 * 4),        s3);
        CPA16(sptr(B3 + (bk + 16) * 72 + n4 * 4), s3 + (size_t)16 * FDIM);
    };

    auto compute = [&](int stg){
        const float* As = sm + stg * 9216;
        const float* B1 = As + 4608;
        const float* B3 = As + 6912;
        const int mrow = wm * 32 + (lane >> 2);
        #pragma unroll
        for (int ks = 0; ks < 4; ks++){
            const int kc4 = ks * 8 + (lane & 3);
            uint32_t a[2][4];
            #pragma unroll
            for (int mf = 0; mf < 2; mf++){
                const float* ap = As + (mrow + mf * 16) * 36 + kc4;
                a[mf][0] = __float_as_uint(ap[0]);
                a[mf][1] = __float_as_uint(ap[8 * 36]);
                a[mf][2] = __float_as_uint(ap[4]);
                a[mf][3] = __float_as_uint(ap[8 * 36 + 4]);
            }
            #pragma unroll
            for (int nf = 0; nf < 4; nf++){
                const int col = wn * 32 + nf * 8 + (lane >> 2);
                const float* bp = B1 + kc4 * 72 + col;
                uint32_t b0 = __float_as_uint(bp[0]);
                uint32_t b1 = __float_as_uint(bp[4 * 72]);
                mma8(acc1[0][nf], a[0], b0, b1);
                mma8(acc1[1][nf], a[1], b0, b1);
                bp = B3 + kc4 * 72 + col;
                b0 = __float_as_uint(bp[0]);
                b1 = __float_as_uint(bp[4 * 72]);
                mma8(acc3[0][nf], a[0], b0, b1);
                mma8(acc3[1][nf], a[1], b0, b1);
            }
        }
    };

    load_chunk(0, 0); CPCOMMIT();
    load_chunk(1, 1); CPCOMMIT();
    #pragma unroll 1
    for (int kc = 0; kc < 32; kc++){
        CPWAIT1();
        __syncthreads();
        compute(kc & 1);
        __syncthreads();
        if (kc + 2 < 32) load_chunk(kc + 2, kc & 1);
        CPCOMMIT();
    }

    float* Hb = g_H + (size_t)e * CAP * FDIM;
    const int colb = n0 + wn * 32 + (lane & 3) * 2;
    #pragma unroll
    for (int mf = 0; mf < 2; mf++){
        #pragma unroll
        for (int r = 0; r < 2; r++){
            int s = m0 + wm * 32 + mf * 16 + (lane >> 2) + r * 8;
            if (s < cnt){
                float* hp = Hb + (size_t)s * FDIM + colb;
                #pragma unroll
                for (int nf = 0; nf < 4; nf++){
                    float c1a = acc1[mf][nf][2 * r], c1b = acc1[mf][nf][2 * r + 1];
                    float c3a = acc3[mf][nf][2 * r], c3b = acc3[mf][nf][2 * r + 1];
                    float ha = (c1a * c3a) / (1.f + __expf(-c1a));   // silu(c1)*c3
                    float hb = (c1b * c3b) / (1.f + __expf(-c1b));
                    float2 v;
                    v.x = __uint_as_float(f2tf(ha));   // pre-round H for GEMM2
                    v.y = __uint_as_float(f2tf(hb));
                    *reinterpret_cast<float2*>(hp + nf * 8) = v;
                }
            }
        }
    }
}

// ---------------- kernel 3: GEMM2 (H@W2)*w_t -> atomic add into out ----------
// BM=128, BN=128, BK=32, 256 thr, warp grid 4x2, warp tile 32x64.
__global__ void __launch_bounds__(256, 2) k_gemm2(
    const float* __restrict__ w2g, float* __restrict__ out)
{
    const int e   = blockIdx.z;
    const int cnt = g_cnt[e];
    const int m0  = blockIdx.x * 128;
    if (m0 >= cnt) return;
    const int n0  = blockIdx.y * 128;

    extern __shared__ float sm[];
    const int tid = threadIdx.x, lane = tid & 31, wid = tid >> 5;
    const int wm = wid & 3, wn = wid >> 2;

    const int am  = tid & 127;
    const int arh = tid >> 7;
    const float* asrc = g_H + (size_t)(e * CAP + m0 + am) * FDIM;
    const float* w2e  = w2g + (size_t)e * FDIM * DDIM;

    float acc[2][8][4];
    #pragma unroll
    for (int i = 0; i < 2; i++)
        #pragma unroll
        for (int j = 0; j < 8; j++)
            #pragma unroll
            for (int k = 0; k < 4; k++) acc[i][j][k] = 0.f;

    auto load_chunk = [&](int kc, int stg){
        float* As = sm + stg * 8960;
        float* Bs = As + 4608;
        const int k0 = kc * 32;
        #pragma unroll
        for (int i = 0; i < 4; i++){
            int kq = arh + 2 * i;
            CPA16(sptr(As + am * 36 + kq * 4), asrc + k0 + kq * 4);
        }
        const int bk = tid >> 5;      // 0..7
        const int n4 = tid & 31;
        const float* s = w2e + (size_t)(k0 + bk) * DDIM + n0 + n4 * 4;
        #pragma unroll
        for (int i = 0; i < 4; i++){
            CPA16(sptr(Bs + (bk + 8 * i) * 136 + n4 * 4), s + (size_t)(8 * i) * DDIM);
        }
    };

    auto compute = [&](int stg){
        const float* As = sm + stg * 8960;
        const float* Bs = As + 4608;
        const int mrow = wm * 32 + (lane >> 2);
        #pragma unroll
        for (int ks = 0; ks < 4; ks++){
            const int kc4 = ks * 8 + (lane & 3);
            uint32_t a[2][4];
            #pragma unroll
            for (int mf = 0; mf < 2; mf++){
                const float* ap = As + (mrow + mf * 16) * 36 + kc4;
                a[mf][0] = __float_as_uint(ap[0]);
                a[mf][1] = __float_as_uint(ap[8 * 36]);
                a[mf][2] = __float_as_uint(ap[4]);
                a[mf][3] = __float_as_uint(ap[8 * 36 + 4]);
            }
            #pragma unroll
            for (int nf = 0; nf < 8; nf++){
                const int col = wn * 64 + nf * 8 + (lane >> 2);
                const float* bp = Bs + kc4 * 136 + col;
                uint32_t b0 = __float_as_uint(bp[0]);
                uint32_t b1 = __float_as_uint(bp[4 * 136]);
                mma8(acc[0][nf], a[0], b0, b1);
                mma8(acc[1][nf], a[1], b0, b1);
            }
        }
    };

    load_chunk(0, 0); CPCOMMIT();
    load_chunk(1, 1); CPCOMMIT();
    #pragma unroll 1
    for (int kc = 0; kc < FDIM / 32; kc++){
        CPWAIT1();
        __syncthreads();
        compute(kc & 1);
        __syncthreads();
        if (kc + 2 < FDIM / 32) load_chunk(kc + 2, kc & 1);
        CPCOMMIT();
    }

    #pragma unroll
    for (int mf = 0; mf < 2; mf++){
        #pragma unroll
        for (int r = 0; r < 2; r++){
            int s = m0 + wm * 32 + mf * 16 + (lane >> 2) + r * 8;
            if (s < cnt){
                int   tok = g_tok[e][s];
                float wt  = g_wt[e][s];
                float* op = out + (size_t)tok * DDIM + n0 + wn * 64 + (lane & 3) * 2;
                #pragma unroll
                for (int nf = 0; nf < 8; nf++){
                    atomicAdd(op + nf * 8,     wt * acc[mf][nf][2 * r]);
                    atomicAdd(op + nf * 8 + 1, wt * acc[mf][nf][2 * r + 1]);
                }
            }
        }
    }
}

// ---------------- launch ----------------
extern "C" void kernel_launch(void* const* d_in, const int* in_sizes, int n_in,
                              void* d_out, int out_size){
    const float* x  = (const float*)d_in[0];
    const float* gw = (const float*)d_in[1];
    const float* w1 = (const float*)d_in[2];
    const float* w2 = (const float*)d_in[3];
    const float* w3 = (const float*)d_in[4];
    float* out = (float*)d_out;

    cudaFuncSetAttribute(k_gemm1, cudaFuncAttributeMaxDynamicSharedMemorySize, 73728);
    cudaFuncSetAttribute(k_gemm2, cudaFuncAttributeMaxDynamicSharedMemorySize, 71680);

    float* xs;  cudaGetSymbolAddress((void**)&xs,  g_X);
    float* w1r; cudaGetSymbolAddress((void**)&w1r, g_W1r);
    float* w3r; cudaGetSymbolAddress((void**)&w3r, g_W3r);
    float* w2r; cudaGetSymbolAddress((void**)&w2r, g_W2r);

    const int n4x = T_TOK * DDIM / 4;
    const int n4w = NEXP * DDIM * FDIM / 4;
    k_zero <<<(n4x + 255) / 256, 256>>>((float4*)out, n4x);
    k_route<<<T_TOK / 8, 256>>>(x, gw);
    k_round<<<(n4x + 255) / 256, 256>>>((const float4*)x, (float4*)xs, n4x);
    k_round<<<8192, 256>>>((const float4*)w1, (float4*)w1r, n4w);
    k_round<<<8192, 256>>>((const float4*)w3, (float4*)w3r, n4w);
    k_round<<<8192, 256>>>((const float4*)w2, (float4*)w2r, n4w);
    // grid x = mtile (fastest) so concurrent CTAs share the same weight tile in L2
    k_gemm1<<<dim3(16, FDIM / 64,  NEXP), 256, 73728>>>(xs, w1r, w3r);
    k_gemm2<<<dim3(16, DDIM / 128, NEXP), 256, 71680>>>(w2r, out);
}

// round 17
// speedup vs baseline: 1.1058x; 1.1058x over previous
#include <cuda_runtime.h>
#include <cstdint>

#define T_TOK 2048
#define DDIM  1024
#define FDIM  4096
#define NEXP  8
#define CAP   2048

// ---------------- scratch (device globals; no allocations) ----------------
__device__ int   g_cnt[NEXP];
__device__ int   g_tok[NEXP][CAP];
__device__ float g_wt [NEXP][CAP];
__device__ float g_X  [(size_t)T_TOK * DDIM];          // tf32-rounded X
__device__ float g_H  [(size_t)NEXP * CAP * FDIM];     // tf32-rounded H

// ---------------- helpers ----------------
__device__ __forceinline__ uint32_t sptr(const void* p){
    return (uint32_t)__cvta_generic_to_shared(p);
}
__device__ __forceinline__ uint32_t f2tf(float f){
    uint32_t u; asm("cvt.rna.tf32.f32 %0, %1;" : "=r"(u) : "f"(f)); return u;
}
#define CPA16(dst, src) asm volatile("cp.async.cg.shared.global [%0], [%1], 16;" :: "r"(dst), "l"(src))
#define CPCOMMIT()      asm volatile("cp.async.commit_group;")
#define CPWAIT1()       asm volatile("cp.async.wait_group 1;")

__device__ __forceinline__ void mma8(float* c, const uint32_t* a, uint32_t b0, uint32_t b1){
    asm volatile("mma.sync.aligned.m16n8k8.row.col.f32.tf32.tf32.f32 "
        "{%0,%1,%2,%3}, {%4,%5,%6,%7}, {%8,%9}, {%0,%1,%2,%3};"
        : "+f"(c[0]),"+f"(c[1]),"+f"(c[2]),"+f"(c[3])
        : "r"(a[0]),"r"(a[1]),"r"(a[2]),"r"(a[3]), "r"(b0),"r"(b1));
}

// ---------------- kernel 0: zero output + counters ----------------
__global__ void k_zero(float4* out, int n4){
    int i = blockIdx.x * 256 + threadIdx.x;
    if (i < NEXP) g_cnt[i] = 0;
    if (i < n4) out[i] = make_float4(0.f, 0.f, 0.f, 0.f);
}

// ---------------- kernel 0b: round X to tf32 (small: 8 MB) --------------
__global__ void k_round(const float4* __restrict__ src, float4* __restrict__ dst, int n4){
    int i = blockIdx.x * 256 + threadIdx.x;
    if (i < n4){
        float4 v = src[i];
        v.x = __uint_as_float(f2tf(v.x));
        v.y = __uint_as_float(f2tf(v.y));
        v.z = __uint_as_float(f2tf(v.z));
        v.w = __uint_as_float(f2tf(v.w));
        dst[i] = v;
    }
}

// ---------------- kernel 1: routing (1 warp per token) ----------------
__global__ void k_route(const float* __restrict__ x, const float* __restrict__ gw){
    const int t    = blockIdx.x * 8 + (threadIdx.x >> 5);
    const int lane = threadIdx.x & 31;
    const float* xr = x + (size_t)t * DDIM;

    float acc[NEXP];
    #pragma unroll
    for (int e = 0; e < NEXP; e++) acc[e] = 0.f;

    for (int i = 0; i < DDIM / 32; i++){
        float xv = xr[i * 32 + lane];
        const float* g = gw + (size_t)(i * 32 + lane) * NEXP;
        #pragma unroll
        for (int e = 0; e < NEXP; e++) acc[e] += xv * g[e];
    }
    #pragma unroll
    for (int e = 0; e < NEXP; e++){
        float v = acc[e];
        #pragma unroll
        for (int off = 16; off > 0; off >>= 1) v += __shfl_xor_sync(0xffffffffu, v, off);
        acc[e] = v;
    }
    if (lane == 0){
        int i0 = 0; float l0 = acc[0];
        #pragma unroll
        for (int e = 1; e < NEXP; e++) if (acc[e] > l0){ l0 = acc[e]; i0 = e; }
        int i1 = -1; float l1 = -3.4e38f;
        #pragma unroll
        for (int e = 0; e < NEXP; e++) if (e != i0 && acc[e] > l1){ l1 = acc[e]; i1 = e; }
        // softmax + top2 renorm == logistic on top-2 logit gap
        float r  = __expf(l1 - l0);
        float w0 = 1.f / (1.f + r);
        float w1 = r * w0;
        int p0 = atomicAdd(&g_cnt[i0], 1);
        g_tok[i0][p0] = t;  g_wt[i0][p0] = w0;
        int p1 = atomicAdd(&g_cnt[i1], 1);
        g_tok[i1][p1] = t;  g_wt[i1][p1] = w1;
    }
}

// ---------------- kernel 2: gathered dual GEMM (X@W1, X@W3) + SwiGLU -> H ----
// BM=128, BN=64 (each of W1/W3), BK=32. 256 thr, warp grid 2(M)x4(N),
// warp tile 64x16 per matrix. 3-stage cp.async, ONE __syncthreads per chunk.
// smem stage = A 128x36 + B1 32x72 + B3 32x72 = 9216 floats.
__global__ void __launch_bounds__(256, 2) k_gemm1(
    const float* __restrict__ x, const float* __restrict__ w1g,
    const float* __restrict__ w3g)
{
    const int e   = blockIdx.z;
    const int cnt = g_cnt[e];
    const int m0  = blockIdx.x * 128;
    if (m0 >= cnt) return;
    const int n0  = blockIdx.y * 64;

    extern __shared__ float sm[];
    const int tid = threadIdx.x, lane = tid & 31, wid = tid >> 5;
    const int wm = wid & 1, wn = wid >> 1;

    const int am  = tid & 127;
    const int arh = tid >> 7;            // 0/1
    const int slot = m0 + am;
    const int tok  = (slot < cnt) ? g_tok[e][slot] : 0;
    const float* asrc = x + (size_t)tok * DDIM;

    const float* w1e = w1g + (size_t)e * DDIM * FDIM;
    const float* w3e = w3g + (size_t)e * DDIM * FDIM;

    float acc1[4][2][4], acc3[4][2][4];
    #pragma unroll
    for (int i = 0; i < 4; i++)
        #pragma unroll
        for (int j = 0; j < 2; j++)
            #pragma unroll
            for (int k = 0; k < 4; k++){ acc1[i][j][k] = 0.f; acc3[i][j][k] = 0.f; }

    auto load_chunk = [&](int kc, int stg){
        float* As = sm + stg * 9216;
        float* B1 = As + 4608;
        float* B3 = As + 6912;
        const int k0 = kc * 32;
        #pragma unroll
        for (int i = 0; i < 4; i++){
            int kq = arh + 2 * i;
            CPA16(sptr(As + am * 36 + kq * 4), asrc + k0 + kq * 4);
        }
        const int bk = tid >> 4;     // 0..15
        const int n4 = tid & 15;
        const float* s1 = w1e + (size_t)(k0 + bk) * FDIM + n0 + n4 * 4;
        CPA16(sptr(B1 + bk * 72 + n4 * 4),        s1);
        CPA16(sptr(B1 + (bk + 16) * 72 + n4 * 4), s1 + (size_t)16 * FDIM);
        const float* s3 = w3e + (size_t)(k0 + bk) * FDIM + n0 + n4 * 4;
        CPA16(sptr(B3 + bk * 72 + n4 * 4),        s3);
        CPA16(sptr(B3 + (bk + 16) * 72 + n4 * 4), s3 + (size_t)16 * FDIM);
    };

    auto compute = [&](int stg){
        const float* As = sm + stg * 9216;
        const float* B1 = As + 4608;
        const float* B3 = As + 6912;
        const int mrow = wm * 64 + (lane >> 2);
        #pragma unroll
        for (int ks = 0; ks < 4; ks++){
            const int kc4 = ks * 8 + (lane & 3);
            uint32_t a[4][4];
            #pragma unroll
            for (int mf = 0; mf < 4; mf++){
                const float* ap = As + (mrow + mf * 16) * 36 + kc4;
                a[mf][0] = __float_as_uint(ap[0]);
                a[mf][1] = __float_as_uint(ap[8 * 36]);
                a[mf][2] = __float_as_uint(ap[4]);
                a[mf][3] = __float_as_uint(ap[8 * 36 + 4]);
            }
            #pragma unroll
            for (int nf = 0; nf < 2; nf++){
                const int col = wn * 16 + nf * 8 + (lane >> 2);
                const float* bp = B1 + kc4 * 72 + col;
                uint32_t b0 = f2tf(bp[0]);
                uint32_t b1 = f2tf(bp[4 * 72]);
                #pragma unroll
                for (int mf = 0; mf < 4; mf++) mma8(acc1[mf][nf], a[mf], b0, b1);
                bp = B3 + kc4 * 72 + col;
                b0 = f2tf(bp[0]);
                b1 = f2tf(bp[4 * 72]);
                #pragma unroll
                for (int mf = 0; mf < 4; mf++) mma8(acc3[mf][nf], a[mf], b0, b1);
            }
        }
    };

    load_chunk(0, 0); CPCOMMIT();
    load_chunk(1, 1); CPCOMMIT();
    #pragma unroll 1
    for (int kc = 0; kc < 32; kc++){
        CPWAIT1();
        __syncthreads();
        if (kc + 2 < 32) load_chunk(kc + 2, (kc + 2) % 3);
        CPCOMMIT();
        compute(kc % 3);
    }

    float* Hb = g_H + (size_t)e * CAP * FDIM;
    const int colb = n0 + wn * 16 + (lane & 3) * 2;
    #pragma unroll
    for (int mf = 0; mf < 4; mf++){
        #pragma unroll
        for (int r = 0; r < 2; r++){
            int s = m0 + wm * 64 + mf * 16 + (lane >> 2) + r * 8;
            if (s < cnt){
                float* hp = Hb + (size_t)s * FDIM + colb;
                #pragma unroll
                for (int nf = 0; nf < 2; nf++){
                    float c1a = acc1[mf][nf][2 * r], c1b = acc1[mf][nf][2 * r + 1];
                    float c3a = acc3[mf][nf][2 * r], c3b = acc3[mf][nf][2 * r + 1];
                    float ha = (c1a * c3a) / (1.f + __expf(-c1a));   // silu(c1)*c3
                    float hb = (c1b * c3b) / (1.f + __expf(-c1b));
                    float2 v;
                    v.x = __uint_as_float(f2tf(ha));   // pre-round H for GEMM2
                    v.y = __uint_as_float(f2tf(hb));
                    *reinterpret_cast<float2*>(hp + nf * 8) = v;
                }
            }
        }
    }
}

// ---------------- kernel 3: GEMM2 (H@W2)*w_t -> atomic add into out ----------
// BM=128, BN=128, BK=32. 256 thr, warp grid 2(M)x4(N), warp tile 64x32.
// 3-stage cp.async, ONE __syncthreads per chunk.
// smem stage = A 128x36 + B 32x136 = 8960 floats.
__global__ void __launch_bounds__(256, 2) k_gemm2(
    const float* __restrict__ w2g, float* __restrict__ out)
{
    const int e   = blockIdx.z;
    const int cnt = g_cnt[e];
    const int m0  = blockIdx.x * 128;
    if (m0 >= cnt) return;
    const int n0  = blockIdx.y * 128;

    extern __shared__ float sm[];
    const int tid = threadIdx.x, lane = tid & 31, wid = tid >> 5;
    const int wm = wid & 1, wn = wid >> 1;

    const int am  = tid & 127;
    const int arh = tid >> 7;
    const float* asrc = g_H + (size_t)(e * CAP + m0 + am) * FDIM;
    const float* w2e  = w2g + (size_t)e * FDIM * DDIM;

    float acc[4][4][4];
    #pragma unroll
    for (int i = 0; i < 4; i++)
        #pragma unroll
        for (int j = 0; j < 4; j++)
            #pragma unroll
            for (int k = 0; k < 4; k++) acc[i][j][k] = 0.f;

    auto load_chunk = [&](int kc, int stg){
        float* As = sm + stg * 8960;
        float* Bs = As + 4608;
        const int k0 = kc * 32;
        #pragma unroll
        for (int i = 0; i < 4; i++){
            int kq = arh + 2 * i;
            CPA16(sptr(As + am * 36 + kq * 4), asrc + k0 + kq * 4);
        }
        const int bk = tid >> 5;      // 0..7
        const int n4 = tid & 31;
        const float* s = w2e + (size_t)(k0 + bk) * DDIM + n0 + n4 * 4;
        #pragma unroll
        for (int i = 0; i < 4; i++){
            CPA16(sptr(Bs + (bk + 8 * i) * 136 + n4 * 4), s + (size_t)(8 * i) * DDIM);
        }
    };

    auto compute = [&](int stg){
        const float* As = sm + stg * 8960;
        const float* Bs = As + 4608;
        const int mrow = wm * 64 + (lane >> 2);
        #pragma unroll
        for (int ks = 0; ks < 4; ks++){
            const int kc4 = ks * 8 + (lane & 3);
            uint32_t a[4][4];
            #pragma unroll
            for (int mf = 0; mf < 4; mf++){
                const float* ap = As + (mrow + mf * 16) * 36 + kc4;
                a[mf][0] = __float_as_uint(ap[0]);
                a[mf][1] = __float_as_uint(ap[8 * 36]);
                a[mf][2] = __float_as_uint(ap[4]);
                a[mf][3] = __float_as_uint(ap[8 * 36 + 4]);
            }
            #pragma unroll
            for (int nf = 0; nf < 4; nf++){
                const int col = wn * 32 + nf * 8 + (lane >> 2);
                const float* bp = Bs + kc4 * 136 + col;
                uint32_t b0 = f2tf(bp[0]);
                uint32_t b1 = f2tf(bp[4 * 136]);
                #pragma unroll
                for (int mf = 0; mf < 4; mf++) mma8(acc[mf][nf], a[mf], b0, b1);
            }
        }
    };

    load_chunk(0, 0); CPCOMMIT();
    load_chunk(1, 1); CPCOMMIT();
    #pragma unroll 1
    for (int kc = 0; kc < FDIM / 32; kc++){
        CPWAIT1();
        __syncthreads();
        if (kc + 2 < FDIM / 32) load_chunk(kc + 2, (kc + 2) % 3);
        CPCOMMIT();
        compute(kc % 3);
    }

    #pragma unroll
    for (int mf = 0; mf < 4; mf++){
        #pragma unroll
        for (int r = 0; r < 2; r++){
            int s = m0 + wm * 64 + mf * 16 + (lane >> 2) + r * 8;
            if (s < cnt){
                int   tok = g_tok[e][s];
                float wt  = g_wt[e][s];
                float* op = out + (size_t)tok * DDIM + n0 + wn * 32 + (lane & 3) * 2;
                #pragma unroll
                for (int nf = 0; nf < 4; nf++){
                    atomicAdd(op + nf * 8,     wt * acc[mf][nf][2 * r]);
                    atomicAdd(op + nf * 8 + 1, wt * acc[mf][nf][2 * r + 1]);
                }
            }
        }
    }
}

// ---------------- launch ----------------
extern "C" void kernel_launch(void* const* d_in, const int* in_sizes, int n_in,
                              void* d_out, int out_size){
    const float* x  = (const float*)d_in[0];
    const float* gw = (const float*)d_in[1];
    const float* w1 = (const float*)d_in[2];
    const float* w2 = (const float*)d_in[3];
    const float* w3 = (const float*)d_in[4];
    float* out = (float*)d_out;

    cudaFuncSetAttribute(k_gemm1, cudaFuncAttributeMaxDynamicSharedMemorySize, 110592);
    cudaFuncSetAttribute(k_gemm2, cudaFuncAttributeMaxDynamicSharedMemorySize, 107520);

    float* xs;  cudaGetSymbolAddress((void**)&xs, g_X);

    const int n4x = T_TOK * DDIM / 4;
    k_zero <<<(n4x + 255) / 256, 256>>>((float4*)out, n4x);
    k_route<<<T_TOK / 8, 256>>>(x, gw);
    k_round<<<(n4x + 255) / 256, 256>>>((const float4*)x, (float4*)xs, n4x);
    // grid x = mtile (fastest) so concurrent CTAs share the same weight tile in L2
    k_gemm1<<<dim3(16, FDIM / 64,  NEXP), 256, 110592>>>(xs, w1, w3);
    k_gemm2<<<dim3(16, DDIM / 128, NEXP), 256, 107520>>>(w2, out);
}